// round 7
// baseline (speedup 1.0000x reference)
#include <cuda_runtime.h>
#include <cuda_bf16.h>

// Leapfrog integrator, GM = 1, A_SCALE = 1. One thread per (particle, stream):
// tid = 2*i + s (s=0 trail, s=1 lead) == output row index -> contiguous stores.
//
// Force scalar 1/(r(1+r)^2 + eps) = u * g^2 with u = rsqrt(s) (1 MUFU/step)
// and g = 1/(1+r) Newton-tracked across steps (2 iterations/step; seed error
// per step is |dh|*g < ~0.05, so 2 quadratic iterations -> ~6e-6 relative).
// Interior kicks fused: one p += dt*a per interior step. cu = c*u computed
// off the Newton critical path; kick = p = fma(cu*g*g, q, p).

__device__ __forceinline__ float rsqrt_approx(float x) {
    float y; asm("rsqrt.approx.f32 %0, %1;" : "=f"(y) : "f"(x)); return y;
}
__device__ __forceinline__ float rcp_approx(float x) {
    float y; asm("rcp.approx.f32 %0, %1;" : "=f"(y) : "f"(x)); return y;
}

struct State {
    float qx, qy, qz, px, py, pz;
    float g;                       // tracked 1/(1+r)
};

__device__ __forceinline__ void kick(State& t, float cf) {
    t.px = fmaf(cf, t.qx, t.px);
    t.py = fmaf(cf, t.qy, t.py);
    t.pz = fmaf(cf, t.qz, t.pz);
}
__device__ __forceinline__ void drift(State& t, float dt) {
    t.qx = fmaf(dt, t.px, t.qx);
    t.qy = fmaf(dt, t.py, t.qy);
    t.qz = fmaf(dt, t.pz, t.qz);
}

// Force eval + kick with coefficient c (= -dt or -dt/2). One MUFU.
__device__ __forceinline__ void force_kick(State& t, float c) {
    float s = fmaf(t.qx, t.qx, fmaf(t.qy, t.qy, fmaf(t.qz, t.qz, 1e-30f)));
    float u = rsqrt_approx(s);          // MUFU, fresh each step
    float cu = c * u;                   // off the Newton chain
    float r = s * u;                    // sqrt(s)
    float h = r + 1.0f;
    float g = t.g;                      // ~1/(1+r_prev)
    g = g * fmaf(-h, g, 2.0f);          // Newton 1
    g = g * fmaf(-h, g, 2.0f);          // Newton 2
    t.g = g;
    kick(t, cu * (g * g));              // cf = c * u * g^2
}

__global__ void __launch_bounds__(32)
stream_integrate_kernel(const float* __restrict__ ts,
                        const float* __restrict__ w_lead,
                        const float* __restrict__ w_trail,
                        const int*   __restrict__ n_steps_p,
                        float* __restrict__ out,
                        int n) {
    int tid = blockIdx.x * blockDim.x + threadIdx.x;
    if (tid >= 2 * n) return;

    int i = tid >> 1;
    int s_ = tid & 1;
    const float* w0 = s_ ? w_lead : w_trail;

    const float2* src = reinterpret_cast<const float2*>(w0 + (size_t)i * 6);
    float2 v0 = src[0];
    float2 v1 = src[1];
    float2 v2 = src[2];

    State st;
    st.qx = v0.x; st.qy = v0.y; st.qz = v1.x;
    st.px = v1.y; st.py = v2.x; st.pz = v2.y;

    float t_f = __ldg(ts + (n - 1)) + 0.001f;
    int   nst = *n_steps_p;
    float dt  = (t_f - ts[i]) / (float)nst;
    float ndt  = -dt;
    float nhdt = 0.5f * ndt;

    // Opening half kick: seed g with a real MUFU rcp + one Newton polish.
    {
        float s = fmaf(st.qx, st.qx, fmaf(st.qy, st.qy, fmaf(st.qz, st.qz, 1e-30f)));
        float u = rsqrt_approx(s);
        float r = s * u;
        float h = r + 1.0f;
        float g = rcp_approx(h);
        g = g * fmaf(-h, g, 2.0f);
        st.g = g;
        kick(st, (nhdt * u) * (g * g));
    }

    if (nst == 64) {
        #pragma unroll 7
        for (int k = 0; k < 63; ++k) {
            drift(st, dt);
            force_kick(st, ndt);
        }
    } else {
        for (int k = 0; k < nst - 1; ++k) {
            drift(st, dt);
            force_kick(st, ndt);
        }
    }

    // Closing step: drift + half kick.
    drift(st, dt);
    force_kick(st, nhdt);

    float2* dst = reinterpret_cast<float2*>(out + (size_t)tid * 6);
    dst[0] = make_float2(st.qx, st.qy);
    dst[1] = make_float2(st.qz, st.px);
    dst[2] = make_float2(st.py, st.pz);
}

extern "C" void kernel_launch(void* const* d_in, const int* in_sizes, int n_in,
                              void* d_out, int out_size) {
    const float* ts      = (const float*)d_in[0];
    const float* w_lead  = (const float*)d_in[1];
    const float* w_trail = (const float*)d_in[2];
    const int*   n_steps = (const int*)d_in[3];
    float*       out     = (float*)d_out;

    int n = in_sizes[0];                 // 65536 particles
    int total = 2 * n;                   // 131072 trajectories
    int block = 32;                      // 4096 CTAs -> 28v27/SM, ~3.6% tail
    int grid = (total + block - 1) / block;
    stream_integrate_kernel<<<grid, block>>>(ts, w_lead, w_trail, n_steps, out, n);
}

// round 9
// speedup vs baseline: 1.0201x; 1.0201x over previous
#include <cuda_runtime.h>
#include <cuda_bf16.h>

// Leapfrog integrator, GM = 1, A_SCALE = 1. One thread per (particle, stream):
// tid = 2*i + s (s=0 trail, s=1 lead) == output row index -> contiguous stores.
//
// Force scalar 1/(r(1+r)^2 + eps) = u * g^2, u = rsqrt(s) (the only MUFU per
// step). g = 1/(1+r) is tracked across steps: seed = previous g, TWO Newton
// iterations (quartic error contraction; worst-case close-passage seed error
// ~0.2 -> 1.6e-3 on that single step, typical ~1e-9 — empirically 2.4e-5
// total, 40x under tolerance). h = 1 + r computed as fma(s, u, 1).
// Interior kicks fused: one p += dt*a per interior step; kick coefficient
// folded: kick = p = fma(cu*g*g, q, p), cu = c*u computed off the chain.

__device__ __forceinline__ float rsqrt_approx(float x) {
    float y; asm("rsqrt.approx.f32 %0, %1;" : "=f"(y) : "f"(x)); return y;
}
__device__ __forceinline__ float rcp_approx(float x) {
    float y; asm("rcp.approx.f32 %0, %1;" : "=f"(y) : "f"(x)); return y;
}

struct State {
    float qx, qy, qz, px, py, pz;
    float g;                       // tracked 1/(1+r)
};

__device__ __forceinline__ void kick(State& t, float cf) {
    t.px = fmaf(cf, t.qx, t.px);
    t.py = fmaf(cf, t.qy, t.py);
    t.pz = fmaf(cf, t.qz, t.pz);
}
__device__ __forceinline__ void drift(State& t, float dt) {
    t.qx = fmaf(dt, t.px, t.qx);
    t.qy = fmaf(dt, t.py, t.qy);
    t.qz = fmaf(dt, t.pz, t.qz);
}

// Force eval + kick with coefficient c (= -dt or -dt/2). 13 FP + 1 MUFU.
__device__ __forceinline__ void force_kick(State& t, float c) {
    float s  = fmaf(t.qx, t.qx, fmaf(t.qy, t.qy, fmaf(t.qz, t.qz, 1e-30f)));
    float u  = rsqrt_approx(s);             // MUFU
    float cu = c * u;                       // off the critical chain
    float h  = fmaf(s, u, 1.0f);            // 1 + r  (r = s*u), single rounding
    float g  = t.g;                         // seed: previous step's 1/(1+r)
    g = g * fmaf(-h, g, 2.0f);              // Newton 1
    g = g * fmaf(-h, g, 2.0f);              // Newton 2
    t.g = g;
    kick(t, cu * (g * g));                  // cf = c * u * g^2
}

__global__ void __launch_bounds__(64)
stream_integrate_kernel(const float* __restrict__ ts,
                        const float* __restrict__ w_lead,
                        const float* __restrict__ w_trail,
                        const int*   __restrict__ n_steps_p,
                        float* __restrict__ out,
                        int n) {
    int tid = blockIdx.x * blockDim.x + threadIdx.x;
    if (tid >= 2 * n) return;

    int i = tid >> 1;
    int s_ = tid & 1;
    const float* w0 = s_ ? w_lead : w_trail;

    const float2* src = reinterpret_cast<const float2*>(w0 + (size_t)i * 6);
    float2 v0 = src[0];
    float2 v1 = src[1];
    float2 v2 = src[2];

    State st;
    st.qx = v0.x; st.qy = v0.y; st.qz = v1.x;
    st.px = v1.y; st.py = v2.x; st.pz = v2.y;

    float t_f = __ldg(ts + (n - 1)) + 0.001f;
    int   nst = *n_steps_p;
    // Fast reciprocal divide: dt = (t_f - ts[i]) / nst. nst = 64 in practice
    // (power of two -> rcp is exact); one Newton polish keeps the general
    // case to ~1 ulp.
    float rn  = rcp_approx((float)nst);
    rn = rn * fmaf(-(float)nst, rn, 2.0f);
    float dt  = (t_f - ts[i]) * rn;
    float ndt  = -dt;
    float nhdt = 0.5f * ndt;

    // Opening half kick: seed g with MUFU rcp + one Newton polish (~1 ulp).
    {
        float s = fmaf(st.qx, st.qx, fmaf(st.qy, st.qy, fmaf(st.qz, st.qz, 1e-30f)));
        float u = rsqrt_approx(s);
        float h = fmaf(s, u, 1.0f);
        float g = rcp_approx(h);
        g = g * fmaf(-h, g, 2.0f);
        st.g = g;
        kick(st, (nhdt * u) * (g * g));
    }

    if (nst == 64) {
        #pragma unroll 7
        for (int k = 0; k < 63; ++k) {
            drift(st, dt);
            force_kick(st, ndt);
        }
    } else {
        for (int k = 0; k < nst - 1; ++k) {
            drift(st, dt);
            force_kick(st, ndt);
        }
    }

    // Closing step: drift + half kick.
    drift(st, dt);
    force_kick(st, nhdt);

    float2* dst = reinterpret_cast<float2*>(out + (size_t)tid * 6);
    dst[0] = make_float2(st.qx, st.qy);
    dst[1] = make_float2(st.qz, st.px);
    dst[2] = make_float2(st.py, st.pz);
}

extern "C" void kernel_launch(void* const* d_in, const int* in_sizes, int n_in,
                              void* d_out, int out_size) {
    const float* ts      = (const float*)d_in[0];
    const float* w_lead  = (const float*)d_in[1];
    const float* w_trail = (const float*)d_in[2];
    const int*   n_steps = (const int*)d_in[3];
    float*       out     = (float*)d_out;

    int n = in_sizes[0];                 // 65536 particles
    int total = 2 * n;                   // 131072 trajectories
    int block = 64;                      // 2048 CTAs, ~28 warps/SM resident
    int grid = (total + block - 1) / block;
    stream_integrate_kernel<<<grid, block>>>(ts, w_lead, w_trail, n_steps, out, n);
}